// round 3
// baseline (speedup 1.0000x reference)
#include <cuda_runtime.h>
#include <math.h>

#define NN 50000
#define EE 625000
#define DD 128
#define MEPS 1e-7f
#define AS_STRIDE 132        // padded A-tile stride (floats)
#define BSTRIDE 64           // per-node edge bucket capacity

// ---------------- device scratch (static; no allocations allowed) ------------
__device__ __align__(16) float g_h  [NN * DD];    // atom-encoder output (read-only after)
__device__ __align__(16) float g_hB [NN * DD];    // residual state (owner-block rows only)
__device__ __align__(16) float g_h2a[NN * DD];    // relu(LN(h)) ping
__device__ __align__(16) float g_h2b[NN * DD];    // relu(LN(h)) pong
__device__ __align__(16) float g_pair[64 * DD];   // combined (a0,a1) bond table
__device__ __align__(16) float g_b2  [8 * DD];    // bond feature-2 table
__device__ int g_cursor[NN];
__device__ int g_packed[NN * BSTRIDE];            // src(16b)|a0<<16|a1<<19|a2<<22

// packed f32x2 FMA (sm_103a)
__device__ __forceinline__ void ffma2(float2& d, const float2& a, const float2& b) {
    asm("fma.rn.f32x2 %0, %1, %2, %0;"
        : "+l"(*reinterpret_cast<unsigned long long*>(&d))
        : "l"(*reinterpret_cast<const unsigned long long*>(&a)),
          "l"(*reinterpret_cast<const unsigned long long*>(&b)));
}

// ---------------- prep: atom encoder + cursor zero + bond tables -------------
__global__ void k_atom(const int* __restrict__ x, const float* __restrict__ aemb,
                       const float* __restrict__ bemb) {
    int i = blockIdx.x * blockDim.x + threadIdx.x;   // NN*32 float4 slots
    if (i >= NN * 32) return;
    int n = i >> 5, q = i & 31;
    if (q == 0) g_cursor[n] = 0;
    if (i < 64 * 32) {                               // pair table: c = a0 | a1<<3
        int c = i >> 5, qq = i & 31;
        float4 u = ((const float4*)(bemb + ((c & 7)     ) * DD))[qq];
        float4 v = ((const float4*)(bemb + (8 + (c >> 3)) * DD))[qq];
        ((float4*)(g_pair + c * DD))[qq] =
            make_float4(u.x + v.x, u.y + v.y, u.z + v.z, u.w + v.w);
    }
    if (i < 8 * 32)                                  // feature-2 table copy
        ((float4*)g_b2)[i] = ((const float4*)(bemb + 16 * DD))[i];
    float4 s = make_float4(0.f, 0.f, 0.f, 0.f);
#pragma unroll
    for (int f = 0; f < 9; ++f) {
        int v = x[n * 9 + f];
        float4 t = ((const float4*)(aemb + (f * 64 + v) * DD))[q];
        s.x += t.x; s.y += t.y; s.z += t.z; s.w += t.w;
    }
    ((float4*)(g_h + n * DD))[q] = s;
}

// ---------------- scatter into fixed-stride buckets (no scan) ----------------
__global__ void k_scatter(const int* __restrict__ src, const int* __restrict__ dst,
                          const int* __restrict__ ea) {
    int e = blockIdx.x * blockDim.x + threadIdx.x;
    if (e >= EE) return;
    int d = dst[e];
    int pos = atomicAdd(&g_cursor[d], 1);
    if (pos < BSTRIDE) {
        int p = src[e] | (ea[e * 3] << 16) | (ea[e * 3 + 1] << 19) | (ea[e * 3 + 2] << 22);
        g_packed[d * BSTRIDE + pos] = p;
    }
}

// ---------------- fused layer: softmax-agg (into smem) + GEMM + LN epilogue --
template <bool RES, bool FINAL>
__global__ void __launch_bounds__(512) k_layer(const float* __restrict__ hin,
                                               float* __restrict__ h2out,
                                               const float* __restrict__ Wl,
                                               const float* __restrict__ bl,
                                               const float* __restrict__ gl,
                                               const float* __restrict__ btl,
                                               float* __restrict__ dout) {
    extern __shared__ float sm[];
    float* SP = sm;                        //  64*128 pair table (32 KB)
    float* S2 = SP + 64 * DD;              //   8*128 a2 table    (4 KB)
    float* Ws = S2 + 8 * DD;               // 128*128 W           (64 KB)
    float* As = Ws + DD * DD;              // 128*AS_STRIDE       (66 KB)
    int tid = threadIdx.x;
    int row0 = blockIdx.x * 128;
    int lane = tid & 31, warp = tid >> 5;

    for (int i = tid; i < 64 * 32; i += 512) ((float4*)SP)[i] = ((const float4*)g_pair)[i];
    if (tid < 8 * 32) ((float4*)S2)[tid] = ((const float4*)g_b2)[tid];
    for (int i = tid; i < DD * DD / 4; i += 512)
        ((float4*)Ws)[i] = ((const float4*)Wl)[i];
    __syncthreads();

    // ---- phase A: aggregation, warp handles 8 consecutive rows ----
    for (int r8 = 0; r8 < 8; ++r8) {
        int row = row0 + warp * 8 + r8;
        float4 o = make_float4(0.f, 0.f, 0.f, 0.f);
        if (row < NN) {
            int deg = g_cursor[row]; if (deg > BSTRIDE) deg = BSTRIDE;
            int base = row * BSTRIDE;
            float4 den = make_float4(0.f, 0.f, 0.f, 0.f);
            float4 num = make_float4(0.f, 0.f, 0.f, 0.f);
            for (int i = 0; i < deg; ++i) {
                int p = __ldg(&g_packed[base + i]);
                const float4 hv = ((const float4*)(hin + (p & 0xFFFF) * DD))[lane];
                const float4 bp = ((const float4*)(SP + ((p >> 16) & 63) * DD))[lane];
                const float4 b2 = ((const float4*)(S2 + ((p >> 22) & 7) * DD))[lane];
                float4 m;
                m.x = fmaxf(hv.x + bp.x + b2.x, 0.f) + MEPS;
                m.y = fmaxf(hv.y + bp.y + b2.y, 0.f) + MEPS;
                m.z = fmaxf(hv.z + bp.z + b2.z, 0.f) + MEPS;
                m.w = fmaxf(hv.w + bp.w + b2.w, 0.f) + MEPS;
                float ex;
                ex = __expf(m.x); den.x += ex; num.x += ex * m.x;
                ex = __expf(m.y); den.y += ex; num.y += ex * m.y;
                ex = __expf(m.z); den.z += ex; num.z += ex * m.z;
                ex = __expf(m.w); den.w += ex; num.w += ex * m.w;
            }
            float4 hn = ((const float4*)(hin + row * DD))[lane];
            o.x = hn.x + num.x / (den.x + 1e-16f);
            o.y = hn.y + num.y / (den.y + 1e-16f);
            o.z = hn.z + num.z / (den.z + 1e-16f);
            o.w = hn.w + num.w / (den.w + 1e-16f);
        }
        ((float4*)(As + (warp * 8 + r8) * AS_STRIDE))[lane] = o;
    }
    __syncthreads();

    // ---- phase B: GEMM (f32x2), 4 rows x 8 cols per thread ----
    int tx = tid & 15, ty = tid >> 4;
    float2 acc[4][4];
#pragma unroll
    for (int r = 0; r < 4; ++r)
#pragma unroll
        for (int j = 0; j < 4; ++j) acc[r][j] = make_float2(0.f, 0.f);

#pragma unroll 2
    for (int k0 = 0; k0 < DD; k0 += 4) {
        float4 a4[4];
#pragma unroll
        for (int r = 0; r < 4; ++r)
            a4[r] = *(const float4*)&As[(ty * 4 + r) * AS_STRIDE + k0];
#pragma unroll
        for (int kk = 0; kk < 4; ++kk) {
            int k = k0 + kk;
            float4 w0 = ((const float4*)(Ws + k * DD))[tx * 2];
            float4 w1 = ((const float4*)(Ws + k * DD))[tx * 2 + 1];
            float2 wp[4] = {{w0.x, w0.y}, {w0.z, w0.w}, {w1.x, w1.y}, {w1.z, w1.w}};
#pragma unroll
            for (int r = 0; r < 4; ++r) {
                float av = (kk == 0) ? a4[r].x : (kk == 1) ? a4[r].y
                         : (kk == 2) ? a4[r].z : a4[r].w;
                float2 ap = make_float2(av, av);
#pragma unroll
                for (int j = 0; j < 4; ++j) ffma2(acc[r][j], ap, wp[j]);
            }
        }
    }

    // ---- epilogue ----
    float4 bA = ((const float4*)(bl))[tx * 2], bB = ((const float4*)(bl))[tx * 2 + 1];
    float4 gA = ((const float4*)(gl))[tx * 2], gB = ((const float4*)(gl))[tx * 2 + 1];
    float4 tA = ((const float4*)(btl))[tx * 2], tB = ((const float4*)(btl))[tx * 2 + 1];
    float bb[8] = {bA.x, bA.y, bA.z, bA.w, bB.x, bB.y, bB.z, bB.w};
    float gg[8] = {gA.x, gA.y, gA.z, gA.w, gB.x, gB.y, gB.z, gB.w};
    float tt[8] = {tA.x, tA.y, tA.z, tA.w, tB.x, tB.y, tB.z, tB.w};

#pragma unroll
    for (int r = 0; r < 4; ++r) {
        int row = row0 + ty * 4 + r;
        int rowc = (row < NN) ? row : (NN - 1);
        float v[8];
#pragma unroll
        for (int j = 0; j < 4; ++j) {
            v[2 * j]     = acc[r][j].x + bb[2 * j];
            v[2 * j + 1] = acc[r][j].y + bb[2 * j + 1];
        }
        if (RES) {
            float4 r0 = ((const float4*)(g_hB + rowc * DD + tx * 8))[0];
            float4 r1 = ((const float4*)(g_hB + rowc * DD + tx * 8))[1];
            v[0] += r0.x; v[1] += r0.y; v[2] += r0.z; v[3] += r0.w;
            v[4] += r1.x; v[5] += r1.y; v[6] += r1.z; v[7] += r1.w;
        }
        float s = 0.f, s2 = 0.f;
#pragma unroll
        for (int j = 0; j < 8; ++j) { s += v[j]; s2 += v[j] * v[j]; }
#pragma unroll
        for (int o = 8; o >= 1; o >>= 1) {
            s  += __shfl_xor_sync(0xffffffffu, s,  o, 16);
            s2 += __shfl_xor_sync(0xffffffffu, s2, o, 16);
        }
        float mu  = s * (1.f / 128.f);
        float var = s2 * (1.f / 128.f) - mu * mu;
        float rs  = rsqrtf(var + 1e-5f);
        float y[8];
#pragma unroll
        for (int j = 0; j < 8; ++j) y[j] = (v[j] - mu) * rs * gg[j] + tt[j];

        if (row < NN) {
            if (FINAL) {
                ((float4*)(dout + row * DD + tx * 8))[0] = make_float4(y[0], y[1], y[2], y[3]);
                ((float4*)(dout + row * DD + tx * 8))[1] = make_float4(y[4], y[5], y[6], y[7]);
            } else {
                ((float4*)(g_hB + row * DD + tx * 8))[0] = make_float4(v[0], v[1], v[2], v[3]);
                ((float4*)(g_hB + row * DD + tx * 8))[1] = make_float4(v[4], v[5], v[6], v[7]);
                ((float4*)(h2out + row * DD + tx * 8))[0] =
                    make_float4(fmaxf(y[0], 0.f), fmaxf(y[1], 0.f), fmaxf(y[2], 0.f), fmaxf(y[3], 0.f));
                ((float4*)(h2out + row * DD + tx * 8))[1] =
                    make_float4(fmaxf(y[4], 0.f), fmaxf(y[5], 0.f), fmaxf(y[6], 0.f), fmaxf(y[7], 0.f));
            }
        }
    }
}

// ---------------- launch ------------------------------------------------------
extern "C" void kernel_launch(void* const* d_in, const int* in_sizes, int n_in,
                              void* d_out, int out_size) {
    const int*   x    = (const int*)  d_in[0];
    const int*   ei   = (const int*)  d_in[1];
    const int*   ea   = (const int*)  d_in[2];
    const float* aemb = (const float*)d_in[3];
    const float* bemb = (const float*)d_in[4];
    const float* W    = (const float*)d_in[5];
    const float* b    = (const float*)d_in[6];
    const float* g    = (const float*)d_in[7];
    const float* bt   = (const float*)d_in[8];
    float* out = (float*)d_out;
    const int* src = ei;
    const int* dst = ei + EE;

    static float *p_h = nullptr, *p_h2a = nullptr, *p_h2b = nullptr;
    if (!p_h) {
        cudaGetSymbolAddress((void**)&p_h,   g_h);
        cudaGetSymbolAddress((void**)&p_h2a, g_h2a);
        cudaGetSymbolAddress((void**)&p_h2b, g_h2b);
        const int SMEM = (64 * DD + 8 * DD + DD * DD + 128 * AS_STRIDE) * (int)sizeof(float);
        cudaFuncSetAttribute((const void*)k_layer<false, false>, cudaFuncAttributeMaxDynamicSharedMemorySize, SMEM);
        cudaFuncSetAttribute((const void*)k_layer<true,  false>, cudaFuncAttributeMaxDynamicSharedMemorySize, SMEM);
        cudaFuncSetAttribute((const void*)k_layer<true,  true >, cudaFuncAttributeMaxDynamicSharedMemorySize, SMEM);
    }
    const int SMEM = (64 * DD + 8 * DD + DD * DD + 128 * AS_STRIDE) * (int)sizeof(float);

    k_atom<<<(NN * 32 + 255) / 256, 256>>>(x, aemb, bemb);     // launch 0
    k_scatter<<<(EE + 255) / 256, 256>>>(src, dst, ea);        // launch 1

    int blocks = (NN + 127) / 128;
    for (int l = 0; l < 7; ++l) {
        const float* Wl  = W  + l * DD * DD;
        const float* bl  = b  + l * DD;
        const float* gl  = g  + l * DD;
        const float* btl = bt + l * DD;
        const float* hi = (l == 0) ? p_h : (((l - 1) & 1) ? p_h2b : p_h2a);
        float* ho = (l & 1) ? p_h2b : p_h2a;
        if (l == 0)
            k_layer<false, false><<<blocks, 512, SMEM>>>(hi, ho, Wl, bl, gl, btl, out);   // launch 2
        else if (l < 6)
            k_layer<true, false><<<blocks, 512, SMEM>>>(hi, ho, Wl, bl, gl, btl, out);    // launch 3 = layer 1 (profiled)
        else
            k_layer<true, true><<<blocks, 512, SMEM>>>(hi, ho, Wl, bl, gl, btl, out);
    }
}

// round 4
// speedup vs baseline: 1.0256x; 1.0256x over previous
#include <cuda_runtime.h>
#include <math.h>

#define NN 50000
#define EE 625000
#define DD 128
#define MEPS 1e-7f
#define AS_STRIDE 132        // padded A-tile stride (floats)
#define BSTRIDE 64           // per-node edge bucket capacity

// ---------------- device scratch (static; no allocations allowed) ------------
__device__ __align__(16) float g_h [NN * DD];    // residual state / layer-0 input
__device__ __align__(16) float g_h2[NN * DD];    // relu(LN(h)) (next conv input)
__device__ __align__(16) float g_A [NN * DD];    // agg output (GEMM input)
__device__ __align__(16) float g_pair[64 * DD];  // combined (a0,a1) bond table
__device__ __align__(16) float g_b2  [8 * DD];   // bond feature-2 table
__device__ int g_cursor[NN];
__device__ int g_deg[NN];                        // clamped degree
__device__ int g_packed[NN * BSTRIDE];           // src(16b)|a0<<16|a1<<19|a2<<22

// packed f32x2 FMA (sm_103a)
__device__ __forceinline__ void ffma2(float2& d, const float2& a, const float2& b) {
    asm("fma.rn.f32x2 %0, %1, %2, %0;"
        : "+l"(*reinterpret_cast<unsigned long long*>(&d))
        : "l"(*reinterpret_cast<const unsigned long long*>(&a)),
          "l"(*reinterpret_cast<const unsigned long long*>(&b)));
}

// ---------------- prep -------------------------------------------------------
__global__ void k_atom(const int* __restrict__ x, const float* __restrict__ aemb,
                       const float* __restrict__ bemb) {
    int i = blockIdx.x * blockDim.x + threadIdx.x;   // NN*32 float4 slots
    if (i >= NN * 32) return;
    int n = i >> 5, q = i & 31;
    if (q == 0) g_cursor[n] = 0;
    if (i < 64 * 32) {                               // pair table: c = a0 | a1<<3
        int c = i >> 5, qq = i & 31;
        float4 u = ((const float4*)(bemb + ((c & 7)     ) * DD))[qq];
        float4 v = ((const float4*)(bemb + (8 + (c >> 3)) * DD))[qq];
        ((float4*)(g_pair + c * DD))[qq] =
            make_float4(u.x + v.x, u.y + v.y, u.z + v.z, u.w + v.w);
    }
    if (i < 8 * 32)
        ((float4*)g_b2)[i] = ((const float4*)(bemb + 16 * DD))[i];
    float4 s = make_float4(0.f, 0.f, 0.f, 0.f);
#pragma unroll
    for (int f = 0; f < 9; ++f) {
        int v = x[n * 9 + f];
        float4 t = ((const float4*)(aemb + (f * 64 + v) * DD))[q];
        s.x += t.x; s.y += t.y; s.z += t.z; s.w += t.w;
    }
    ((float4*)(g_h + n * DD))[q] = s;
}

__global__ void k_scatter(const int* __restrict__ src, const int* __restrict__ dst,
                          const int* __restrict__ ea) {
    int e = blockIdx.x * blockDim.x + threadIdx.x;
    if (e >= EE) return;
    int d = dst[e];
    int pos = atomicAdd(&g_cursor[d], 1);
    if (pos < BSTRIDE) {
        int p = src[e] | (ea[e * 3] << 16) | (ea[e * 3 + 1] << 19) | (ea[e * 3 + 2] << 22);
        g_packed[d * BSTRIDE + pos] = p;
    }
}

__global__ void k_clamp() {
    int n = blockIdx.x * blockDim.x + threadIdx.x;
    if (n < NN) {
        int d = g_cursor[n];
        g_deg[n] = (d > BSTRIDE) ? BSTRIDE : d;
    }
}

// ---------------- aggregation: warp/node, register-resident bucket, unroll-2 -
__global__ void __launch_bounds__(256, 4) k_agg(const float* __restrict__ hin) {
    __shared__ float SP[64 * DD];          // 32 KB pair table
    __shared__ float S2[8 * DD];           //  4 KB feature-2 table
    int tid = threadIdx.x;
    for (int i = tid; i < 64 * 32; i += 256) ((float4*)SP)[i] = ((const float4*)g_pair)[i];
    if (tid < 8 * 32) ((float4*)S2)[tid] = ((const float4*)g_b2)[tid];
    __syncthreads();

    int warp = tid >> 5, lane = tid & 31;
    int n = blockIdx.x * 8 + warp;
    if (n >= NN) return;
    int deg = g_deg[n];
    int base = n * BSTRIDE;

    // whole bucket into 2 registers per lane (reads past deg are allocated mem)
    int pk0 = g_packed[base + lane];
    int pk1 = g_packed[base + 32 + lane];

    float4 den = make_float4(0.f, 0.f, 0.f, 0.f);
    float4 num = make_float4(0.f, 0.f, 0.f, 0.f);

    int degR = (deg + 1) & ~1;
    for (int i = 0; i < degR; i += 2) {
        int p0 = __shfl_sync(0xffffffffu, (i < 32) ? pk0 : pk1, i & 31);
        int j = i + 1;
        int p1 = __shfl_sync(0xffffffffu, (j < 32) ? pk0 : pk1, j & 31);

        int s0 = p0 & 0xFFFF; if (s0 >= NN) s0 = 0;
        int s1 = p1 & 0xFFFF; if (s1 >= NN) s1 = 0;
        float f0 = 1.f;                       // i < deg always (i < degR <= deg+1, i even)
        float f1 = (j < deg) ? 1.f : 0.f;

        const float4 hv0 = __ldg(((const float4*)(hin + s0 * DD)) + lane);
        const float4 hv1 = __ldg(((const float4*)(hin + s1 * DD)) + lane);
        const float4 c0 = ((const float4*)(SP + ((p0 >> 16) & 63) * DD))[lane];
        const float4 c1 = ((const float4*)(SP + ((p1 >> 16) & 63) * DD))[lane];
        const float4 d0 = ((const float4*)(S2 + ((p0 >> 22) & 7) * DD))[lane];
        const float4 d1 = ((const float4*)(S2 + ((p1 >> 22) & 7) * DD))[lane];

        float4 m0, m1;
        m0.x = fmaxf(hv0.x + c0.x + d0.x, 0.f) + MEPS;
        m0.y = fmaxf(hv0.y + c0.y + d0.y, 0.f) + MEPS;
        m0.z = fmaxf(hv0.z + c0.z + d0.z, 0.f) + MEPS;
        m0.w = fmaxf(hv0.w + c0.w + d0.w, 0.f) + MEPS;
        m1.x = fmaxf(hv1.x + c1.x + d1.x, 0.f) + MEPS;
        m1.y = fmaxf(hv1.y + c1.y + d1.y, 0.f) + MEPS;
        m1.z = fmaxf(hv1.z + c1.z + d1.z, 0.f) + MEPS;
        m1.w = fmaxf(hv1.w + c1.w + d1.w, 0.f) + MEPS;

        float e;
        e = __expf(m0.x) * f0; den.x += e; num.x += e * m0.x;
        e = __expf(m0.y) * f0; den.y += e; num.y += e * m0.y;
        e = __expf(m0.z) * f0; den.z += e; num.z += e * m0.z;
        e = __expf(m0.w) * f0; den.w += e; num.w += e * m0.w;
        e = __expf(m1.x) * f1; den.x += e; num.x += e * m1.x;
        e = __expf(m1.y) * f1; den.y += e; num.y += e * m1.y;
        e = __expf(m1.z) * f1; den.z += e; num.z += e * m1.z;
        e = __expf(m1.w) * f1; den.w += e; num.w += e * m1.w;
    }

    float4 hn = ((const float4*)(hin + n * DD))[lane];
    float4 o;
    o.x = hn.x + num.x / (den.x + 1e-16f);
    o.y = hn.y + num.y / (den.y + 1e-16f);
    o.z = hn.z + num.z / (den.z + 1e-16f);
    o.w = hn.w + num.w / (den.w + 1e-16f);
    ((float4*)(g_A + n * DD))[lane] = o;
}

// ---------------- GEMM (f32x2) + bias + residual + LN(+ReLU), 64-row tiles ---
template <bool RES, bool FINAL>
__global__ void __launch_bounds__(256, 2) k_gemm(const float* __restrict__ Wl,
                                                 const float* __restrict__ bl,
                                                 const float* __restrict__ gl,
                                                 const float* __restrict__ btl,
                                                 float* __restrict__ dout) {
    extern __shared__ float sm[];
    float* Ws = sm;                       // 128x128 (64 KB)
    float* As = sm + DD * DD;             // 64 x AS_STRIDE (33.8 KB)
    int tid = threadIdx.x;
    int row0 = blockIdx.x * 64;

    for (int i = tid; i < DD * DD / 4; i += 256)
        ((float4*)Ws)[i] = ((const float4*)Wl)[i];
    for (int i = tid; i < 64 * 32; i += 256) {
        int r = i >> 5, q = i & 31;
        int grow = row0 + r;
        float4 v = (grow < NN) ? ((const float4*)(g_A + grow * DD))[q]
                               : make_float4(0.f, 0.f, 0.f, 0.f);
        ((float4*)(As + r * AS_STRIDE))[q] = v;
    }
    __syncthreads();

    int tx = tid & 15, ty = tid >> 4;     // tx: 8 cols (4 f32x2), ty: 4 rows of 64
    float2 acc[4][4];
#pragma unroll
    for (int r = 0; r < 4; ++r)
#pragma unroll
        for (int j = 0; j < 4; ++j) acc[r][j] = make_float2(0.f, 0.f);

#pragma unroll 2
    for (int k0 = 0; k0 < DD; k0 += 4) {
        float4 a4[4];
#pragma unroll
        for (int r = 0; r < 4; ++r)
            a4[r] = *(const float4*)&As[(ty * 4 + r) * AS_STRIDE + k0];
#pragma unroll
        for (int kk = 0; kk < 4; ++kk) {
            int k = k0 + kk;
            float4 w0 = ((const float4*)(Ws + k * DD))[tx * 2];
            float4 w1 = ((const float4*)(Ws + k * DD))[tx * 2 + 1];
            float2 wp[4] = {{w0.x, w0.y}, {w0.z, w0.w}, {w1.x, w1.y}, {w1.z, w1.w}};
#pragma unroll
            for (int r = 0; r < 4; ++r) {
                float av = (kk == 0) ? a4[r].x : (kk == 1) ? a4[r].y
                         : (kk == 2) ? a4[r].z : a4[r].w;
                float2 ap = make_float2(av, av);
#pragma unroll
                for (int j = 0; j < 4; ++j) ffma2(acc[r][j], ap, wp[j]);
            }
        }
    }

    float4 bA = ((const float4*)(bl))[tx * 2], bB = ((const float4*)(bl))[tx * 2 + 1];
    float4 gA = ((const float4*)(gl))[tx * 2], gB = ((const float4*)(gl))[tx * 2 + 1];
    float4 tA = ((const float4*)(btl))[tx * 2], tB = ((const float4*)(btl))[tx * 2 + 1];
    float bb[8] = {bA.x, bA.y, bA.z, bA.w, bB.x, bB.y, bB.z, bB.w};
    float gg[8] = {gA.x, gA.y, gA.z, gA.w, gB.x, gB.y, gB.z, gB.w};
    float tt[8] = {tA.x, tA.y, tA.z, tA.w, tB.x, tB.y, tB.z, tB.w};

#pragma unroll
    for (int r = 0; r < 4; ++r) {
        int row = row0 + ty * 4 + r;
        int rowc = (row < NN) ? row : (NN - 1);   // clamp stays inside this block's tile
        float v[8];
#pragma unroll
        for (int j = 0; j < 4; ++j) {
            v[2 * j]     = acc[r][j].x + bb[2 * j];
            v[2 * j + 1] = acc[r][j].y + bb[2 * j + 1];
        }
        if (RES) {
            float4 r0 = ((const float4*)(g_h + rowc * DD + tx * 8))[0];
            float4 r1 = ((const float4*)(g_h + rowc * DD + tx * 8))[1];
            v[0] += r0.x; v[1] += r0.y; v[2] += r0.z; v[3] += r0.w;
            v[4] += r1.x; v[5] += r1.y; v[6] += r1.z; v[7] += r1.w;
        }
        float s = 0.f, s2 = 0.f;
#pragma unroll
        for (int j = 0; j < 8; ++j) { s += v[j]; s2 += v[j] * v[j]; }
#pragma unroll
        for (int o = 8; o >= 1; o >>= 1) {
            s  += __shfl_xor_sync(0xffffffffu, s,  o, 16);
            s2 += __shfl_xor_sync(0xffffffffu, s2, o, 16);
        }
        float mu  = s * (1.f / 128.f);
        float var = s2 * (1.f / 128.f) - mu * mu;
        float rs  = rsqrtf(var + 1e-5f);
        float y[8];
#pragma unroll
        for (int j = 0; j < 8; ++j) y[j] = (v[j] - mu) * rs * gg[j] + tt[j];

        if (row < NN) {
            if (FINAL) {
                ((float4*)(dout + row * DD + tx * 8))[0] = make_float4(y[0], y[1], y[2], y[3]);
                ((float4*)(dout + row * DD + tx * 8))[1] = make_float4(y[4], y[5], y[6], y[7]);
            } else {
                ((float4*)(g_h + row * DD + tx * 8))[0] = make_float4(v[0], v[1], v[2], v[3]);
                ((float4*)(g_h + row * DD + tx * 8))[1] = make_float4(v[4], v[5], v[6], v[7]);
                ((float4*)(g_h2 + row * DD + tx * 8))[0] =
                    make_float4(fmaxf(y[0], 0.f), fmaxf(y[1], 0.f), fmaxf(y[2], 0.f), fmaxf(y[3], 0.f));
                ((float4*)(g_h2 + row * DD + tx * 8))[1] =
                    make_float4(fmaxf(y[4], 0.f), fmaxf(y[5], 0.f), fmaxf(y[6], 0.f), fmaxf(y[7], 0.f));
            }
        }
    }
}

// ---------------- launch ------------------------------------------------------
extern "C" void kernel_launch(void* const* d_in, const int* in_sizes, int n_in,
                              void* d_out, int out_size) {
    const int*   x    = (const int*)  d_in[0];
    const int*   ei   = (const int*)  d_in[1];
    const int*   ea   = (const int*)  d_in[2];
    const float* aemb = (const float*)d_in[3];
    const float* bemb = (const float*)d_in[4];
    const float* W    = (const float*)d_in[5];
    const float* b    = (const float*)d_in[6];
    const float* g    = (const float*)d_in[7];
    const float* bt   = (const float*)d_in[8];
    float* out = (float*)d_out;
    const int* src = ei;
    const int* dst = ei + EE;

    static float *p_h = nullptr, *p_h2 = nullptr;
    const int SMEM = (DD * DD + 64 * AS_STRIDE) * (int)sizeof(float);  // ~99 KB
    if (!p_h) {
        cudaGetSymbolAddress((void**)&p_h,  g_h);
        cudaGetSymbolAddress((void**)&p_h2, g_h2);
        cudaFuncSetAttribute((const void*)k_gemm<false, false>, cudaFuncAttributeMaxDynamicSharedMemorySize, SMEM);
        cudaFuncSetAttribute((const void*)k_gemm<true,  false>, cudaFuncAttributeMaxDynamicSharedMemorySize, SMEM);
        cudaFuncSetAttribute((const void*)k_gemm<true,  true >, cudaFuncAttributeMaxDynamicSharedMemorySize, SMEM);
    }

    k_atom<<<(NN * 32 + 255) / 256, 256>>>(x, aemb, bemb);     // launch 0
    k_scatter<<<(EE + 255) / 256, 256>>>(src, dst, ea);        // launch 1
    k_clamp<<<(NN + 255) / 256, 256>>>();                      // launch 2

    int agg_blocks  = (NN + 7) / 8;
    int gemm_blocks = (NN + 63) / 64;
    for (int l = 0; l < 7; ++l) {
        const float* Wl  = W  + l * DD * DD;
        const float* bl  = b  + l * DD;
        const float* gl  = g  + l * DD;
        const float* btl = bt + l * DD;
        const float* hi = (l == 0) ? p_h : p_h2;
        k_agg<<<agg_blocks, 256>>>(hi);                        // launch 3 = agg0 (profiled)
        if (l == 0)
            k_gemm<false, false><<<gemm_blocks, 256, SMEM>>>(Wl, bl, gl, btl, out);
        else if (l < 6)
            k_gemm<true, false><<<gemm_blocks, 256, SMEM>>>(Wl, bl, gl, btl, out);
        else
            k_gemm<true, true><<<gemm_blocks, 256, SMEM>>>(Wl, bl, gl, btl, out);
    }
}

// round 5
// speedup vs baseline: 1.2040x; 1.1740x over previous
#include <cuda_runtime.h>
#include <cuda_pipeline_primitives.h>
#include <math.h>

#define NN 50000
#define EE 625000
#define DD 128
#define MEPS 1e-7f
#define AS_STRIDE 132        // padded A-tile stride (floats)
#define BSTRIDE 64           // per-node edge bucket capacity

// ---------------- device scratch (static; no allocations allowed) ------------
__device__ __align__(16) float g_h [NN * DD];    // residual state / layer-0 input
__device__ __align__(16) float g_h2[NN * DD];    // relu(LN(h)) (next conv input)
__device__ __align__(16) float g_A [NN * DD];    // agg output (GEMM input)
__device__ __align__(16) float g_pair[64 * DD];  // combined (a0,a1) bond table
__device__ __align__(16) float g_b2  [8 * DD];   // bond feature-2 table
__device__ int g_cursor[NN];
__device__ int g_deg[NN];                        // clamped degree
__device__ int g_packed[NN * BSTRIDE];           // src(16b)|a0<<16|a1<<19|a2<<22

// ---------------- packed f32x2 helpers (sm_103a) ------------------------------
__device__ __forceinline__ unsigned long long f2u(float2 v) {
    return *reinterpret_cast<unsigned long long*>(&v);
}
__device__ __forceinline__ float2 u2f(unsigned long long v) {
    return *reinterpret_cast<float2*>(&v);
}
__device__ __forceinline__ float2 f2add(float2 a, float2 b) {
    unsigned long long d;
    asm("add.rn.f32x2 %0,%1,%2;" : "=l"(d) : "l"(f2u(a)), "l"(f2u(b)));
    return u2f(d);
}
__device__ __forceinline__ float2 f2fma(float2 a, float2 b, float2 c) {
    unsigned long long d;
    asm("fma.rn.f32x2 %0,%1,%2,%3;" : "=l"(d) : "l"(f2u(a)), "l"(f2u(b)), "l"(f2u(c)));
    return u2f(d);
}
__device__ __forceinline__ void ffma2(float2& d, const float2& a, const float2& b) {
    asm("fma.rn.f32x2 %0, %1, %2, %0;"
        : "+l"(*reinterpret_cast<unsigned long long*>(&d))
        : "l"(*reinterpret_cast<const unsigned long long*>(&a)),
          "l"(*reinterpret_cast<const unsigned long long*>(&b)));
}

// ---------------- prep -------------------------------------------------------
__global__ void k_atom(const int* __restrict__ x, const float* __restrict__ aemb,
                       const float* __restrict__ bemb) {
    int i = blockIdx.x * blockDim.x + threadIdx.x;   // NN*32 float4 slots
    if (i >= NN * 32) return;
    int n = i >> 5, q = i & 31;
    if (q == 0) g_cursor[n] = 0;
    if (i < 64 * 32) {                               // pair table: c = a0 | a1<<3
        int c = i >> 5, qq = i & 31;
        float4 u = ((const float4*)(bemb + ((c & 7)     ) * DD))[qq];
        float4 v = ((const float4*)(bemb + (8 + (c >> 3)) * DD))[qq];
        ((float4*)(g_pair + c * DD))[qq] =
            make_float4(u.x + v.x, u.y + v.y, u.z + v.z, u.w + v.w);
    }
    if (i < 8 * 32)
        ((float4*)g_b2)[i] = ((const float4*)(bemb + 16 * DD))[i];
    float4 s = make_float4(0.f, 0.f, 0.f, 0.f);
#pragma unroll
    for (int f = 0; f < 9; ++f) {
        int v = x[n * 9 + f];
        float4 t = ((const float4*)(aemb + (f * 64 + v) * DD))[q];
        s.x += t.x; s.y += t.y; s.z += t.z; s.w += t.w;
    }
    ((float4*)(g_h + n * DD))[q] = s;
}

__global__ void k_scatter(const int* __restrict__ src, const int* __restrict__ dst,
                          const int* __restrict__ ea) {
    int e = blockIdx.x * blockDim.x + threadIdx.x;
    if (e >= EE) return;
    int d = dst[e];
    int pos = atomicAdd(&g_cursor[d], 1);
    if (pos < BSTRIDE) {
        int p = src[e] | (ea[e * 3] << 16) | (ea[e * 3 + 1] << 19) | (ea[e * 3 + 2] << 22);
        g_packed[d * BSTRIDE + pos] = p;
    }
}

__global__ void k_clamp() {
    int n = blockIdx.x * blockDim.x + threadIdx.x;
    if (n < NN) {
        int d = g_cursor[n];
        g_deg[n] = (d > BSTRIDE) ? BSTRIDE : d;
    }
}

// ---------------- aggregation: persistent CTAs, warp/node, packed f32x2 ------
__global__ void __launch_bounds__(256, 5) k_agg(const float* __restrict__ hin) {
    __shared__ float SP[64 * DD];          // 32 KB pair table
    __shared__ float S2[8 * DD];           //  4 KB feature-2 table
    int tid = threadIdx.x;
    for (int i = tid; i < 64 * 32; i += 256) ((float4*)SP)[i] = ((const float4*)g_pair)[i];
    if (tid < 8 * 32) ((float4*)S2)[tid] = ((const float4*)g_b2)[tid];
    __syncthreads();

    int warp = tid >> 5, lane = tid & 31;
    const float4* SPl = (const float4*)SP + lane;   // + combo*32
    const float4* S2l = (const float4*)S2 + lane;   // + a2*32
    const float4* Hl  = (const float4*)hin + lane;  // + src*32
    const float2 eps2 = make_float2(MEPS, MEPS);

    for (int n = blockIdx.x * 8 + warp; n < NN; n += gridDim.x * 8) {
        int deg = g_deg[n];
        int base = n * BSTRIDE;
        int pk0 = g_packed[base + lane];
        int pk1 = g_packed[base + 32 + lane];

        float2 den01 = make_float2(0.f, 0.f), den23 = make_float2(0.f, 0.f);
        float2 num01 = make_float2(0.f, 0.f), num23 = make_float2(0.f, 0.f);

        auto proc = [&](int p) {
            const float4 hv = __ldg(Hl + (p & 0xFFFF) * 32);
            const float4 c  = SPl[((p >> 16) & 63) * 32];
            const float4 d  = S2l[((p >> 22) & 7) * 32];
            float2 t01 = f2add(make_float2(hv.x, hv.y), make_float2(c.x, c.y));
            float2 t23 = f2add(make_float2(hv.z, hv.w), make_float2(c.z, c.w));
            t01 = f2add(t01, make_float2(d.x, d.y));
            t23 = f2add(t23, make_float2(d.z, d.w));
            float2 m01 = f2add(make_float2(fmaxf(t01.x, 0.f), fmaxf(t01.y, 0.f)), eps2);
            float2 m23 = f2add(make_float2(fmaxf(t23.x, 0.f), fmaxf(t23.y, 0.f)), eps2);
            float2 e01 = make_float2(__expf(m01.x), __expf(m01.y));
            float2 e23 = make_float2(__expf(m23.x), __expf(m23.y));
            den01 = f2add(den01, e01);  den23 = f2add(den23, e23);
            num01 = f2fma(e01, m01, num01);  num23 = f2fma(e23, m23, num23);
        };

        int pairs = deg & ~1;
        for (int i = 0; i < pairs; i += 2) {
            int p0 = __shfl_sync(0xffffffffu, (i < 32) ? pk0 : pk1, i & 31);
            int j = i + 1;
            int p1 = __shfl_sync(0xffffffffu, (j < 32) ? pk0 : pk1, j & 31);
            proc(p0);
            proc(p1);
        }
        if (deg & 1) {
            int p = __shfl_sync(0xffffffffu, (pairs < 32) ? pk0 : pk1, pairs & 31);
            proc(p);
        }

        float4 hn = __ldg(Hl + n * 32);
        float4 o;
        o.x = hn.x + num01.x / (den01.x + 1e-16f);
        o.y = hn.y + num01.y / (den01.y + 1e-16f);
        o.z = hn.z + num23.x / (den23.x + 1e-16f);
        o.w = hn.w + num23.y / (den23.y + 1e-16f);
        ((float4*)(g_A + n * DD))[lane] = o;
    }
}

// ---------------- persistent GEMM (f32x2) + cp.async double-buffered A tiles -
template <bool RES, bool FINAL>
__global__ void __launch_bounds__(512) k_gemm(const float* __restrict__ Wl,
                                              const float* __restrict__ bl,
                                              const float* __restrict__ gl,
                                              const float* __restrict__ btl,
                                              float* __restrict__ dout) {
    extern __shared__ float sm[];
    float* Ws = sm;                                   // 128x128 (64 KB)
    float* Ab0 = sm + DD * DD;                        // 128 x AS_STRIDE
    float* Ab1 = Ab0 + 128 * AS_STRIDE;               // 128 x AS_STRIDE
    int tid = threadIdx.x;

    for (int i = tid; i < DD * DD / 4; i += 512)
        ((float4*)Ws)[i] = ((const float4*)Wl)[i];

    const int ntiles = (NN + 127) / 128;
    int t = blockIdx.x;

    // prefetch first tile into Ab0
    if (t < ntiles) {
        int row0 = t * 128;
        for (int i = tid; i < 128 * 32; i += 512) {
            int r = i >> 5, q = i & 31;
            int grow = row0 + r;
            int rc = (grow < NN) ? grow : 0;
            __pipeline_memcpy_async(&Ab0[r * AS_STRIDE + q * 4], &g_A[rc * DD + q * 4],
                                    16, (grow < NN) ? 0 : 16);
        }
    }
    __pipeline_commit();

    int tx = tid & 15, ty = tid >> 4;   // tx: 8 cols (4 f32x2); ty: 4 rows of 128
    float4 bA = ((const float4*)(bl))[tx * 2], bB = ((const float4*)(bl))[tx * 2 + 1];
    float4 gA = ((const float4*)(gl))[tx * 2], gB = ((const float4*)(gl))[tx * 2 + 1];
    float4 tA = ((const float4*)(btl))[tx * 2], tB = ((const float4*)(btl))[tx * 2 + 1];
    float bb[8] = {bA.x, bA.y, bA.z, bA.w, bB.x, bB.y, bB.z, bB.w};
    float gg[8] = {gA.x, gA.y, gA.z, gA.w, gB.x, gB.y, gB.z, gB.w};
    float tt[8] = {tA.x, tA.y, tA.z, tA.w, tB.x, tB.y, tB.z, tB.w};

    int buf = 0;
    for (; t < ntiles; t += gridDim.x) {
        __pipeline_wait_prior(0);
        __syncthreads();                 // tile data visible to all threads (also covers Ws on iter 0)

        int tn = t + gridDim.x;
        float* An = buf ? Ab0 : Ab1;
        if (tn < ntiles) {
            int row0n = tn * 128;
            for (int i = tid; i < 128 * 32; i += 512) {
                int r = i >> 5, q = i & 31;
                int grow = row0n + r;
                int rc = (grow < NN) ? grow : 0;
                __pipeline_memcpy_async(&An[r * AS_STRIDE + q * 4], &g_A[rc * DD + q * 4],
                                        16, (grow < NN) ? 0 : 16);
            }
        }
        __pipeline_commit();

        const float* As = buf ? Ab1 : Ab0;
        int row0 = t * 128;

        float2 acc[4][4];
#pragma unroll
        for (int r = 0; r < 4; ++r)
#pragma unroll
            for (int j = 0; j < 4; ++j) acc[r][j] = make_float2(0.f, 0.f);

#pragma unroll 2
        for (int k0 = 0; k0 < DD; k0 += 4) {
            float4 a4[4];
#pragma unroll
            for (int r = 0; r < 4; ++r)
                a4[r] = *(const float4*)&As[(ty * 4 + r) * AS_STRIDE + k0];
#pragma unroll
            for (int kk = 0; kk < 4; ++kk) {
                int k = k0 + kk;
                float4 w0 = ((const float4*)(Ws + k * DD))[tx * 2];
                float4 w1 = ((const float4*)(Ws + k * DD))[tx * 2 + 1];
                float2 wp[4] = {{w0.x, w0.y}, {w0.z, w0.w}, {w1.x, w1.y}, {w1.z, w1.w}};
#pragma unroll
                for (int r = 0; r < 4; ++r) {
                    float av = (kk == 0) ? a4[r].x : (kk == 1) ? a4[r].y
                             : (kk == 2) ? a4[r].z : a4[r].w;
                    float2 ap = make_float2(av, av);
#pragma unroll
                    for (int j = 0; j < 4; ++j) ffma2(acc[r][j], ap, wp[j]);
                }
            }
        }

#pragma unroll
        for (int r = 0; r < 4; ++r) {
            int row = row0 + ty * 4 + r;
            int rowc = (row < NN) ? row : (NN - 1);
            float v[8];
#pragma unroll
            for (int j = 0; j < 4; ++j) {
                v[2 * j]     = acc[r][j].x + bb[2 * j];
                v[2 * j + 1] = acc[r][j].y + bb[2 * j + 1];
            }
            if (RES) {
                float4 r0 = ((const float4*)(g_h + rowc * DD + tx * 8))[0];
                float4 r1 = ((const float4*)(g_h + rowc * DD + tx * 8))[1];
                v[0] += r0.x; v[1] += r0.y; v[2] += r0.z; v[3] += r0.w;
                v[4] += r1.x; v[5] += r1.y; v[6] += r1.z; v[7] += r1.w;
            }
            float s = 0.f, s2 = 0.f;
#pragma unroll
            for (int j = 0; j < 8; ++j) { s += v[j]; s2 += v[j] * v[j]; }
#pragma unroll
            for (int o = 8; o >= 1; o >>= 1) {
                s  += __shfl_xor_sync(0xffffffffu, s,  o, 16);
                s2 += __shfl_xor_sync(0xffffffffu, s2, o, 16);
            }
            float mu  = s * (1.f / 128.f);
            float var = s2 * (1.f / 128.f) - mu * mu;
            float rs  = rsqrtf(var + 1e-5f);
            float y[8];
#pragma unroll
            for (int j = 0; j < 8; ++j) y[j] = (v[j] - mu) * rs * gg[j] + tt[j];

            if (row < NN) {
                if (FINAL) {
                    ((float4*)(dout + row * DD + tx * 8))[0] = make_float4(y[0], y[1], y[2], y[3]);
                    ((float4*)(dout + row * DD + tx * 8))[1] = make_float4(y[4], y[5], y[6], y[7]);
                } else {
                    ((float4*)(g_h + row * DD + tx * 8))[0] = make_float4(v[0], v[1], v[2], v[3]);
                    ((float4*)(g_h + row * DD + tx * 8))[1] = make_float4(v[4], v[5], v[6], v[7]);
                    ((float4*)(g_h2 + row * DD + tx * 8))[0] =
                        make_float4(fmaxf(y[0], 0.f), fmaxf(y[1], 0.f), fmaxf(y[2], 0.f), fmaxf(y[3], 0.f));
                    ((float4*)(g_h2 + row * DD + tx * 8))[1] =
                        make_float4(fmaxf(y[4], 0.f), fmaxf(y[5], 0.f), fmaxf(y[6], 0.f), fmaxf(y[7], 0.f));
                }
            }
        }
        buf ^= 1;
        __syncthreads();   // protect the buffer we just computed from next prefetch
    }
}

// ---------------- launch ------------------------------------------------------
extern "C" void kernel_launch(void* const* d_in, const int* in_sizes, int n_in,
                              void* d_out, int out_size) {
    const int*   x    = (const int*)  d_in[0];
    const int*   ei   = (const int*)  d_in[1];
    const int*   ea   = (const int*)  d_in[2];
    const float* aemb = (const float*)d_in[3];
    const float* bemb = (const float*)d_in[4];
    const float* W    = (const float*)d_in[5];
    const float* b    = (const float*)d_in[6];
    const float* g    = (const float*)d_in[7];
    const float* bt   = (const float*)d_in[8];
    float* out = (float*)d_out;
    const int* src = ei;
    const int* dst = ei + EE;

    static float *p_h = nullptr, *p_h2 = nullptr;
    static int sms = 148;
    const int GSMEM = (DD * DD + 2 * 128 * AS_STRIDE) * (int)sizeof(float);  // ~196 KB
    if (!p_h) {
        cudaGetSymbolAddress((void**)&p_h,  g_h);
        cudaGetSymbolAddress((void**)&p_h2, g_h2);
        cudaDeviceGetAttribute(&sms, cudaDevAttrMultiProcessorCount, 0);
        cudaFuncSetAttribute((const void*)k_gemm<false, false>, cudaFuncAttributeMaxDynamicSharedMemorySize, GSMEM);
        cudaFuncSetAttribute((const void*)k_gemm<true,  false>, cudaFuncAttributeMaxDynamicSharedMemorySize, GSMEM);
        cudaFuncSetAttribute((const void*)k_gemm<true,  true >, cudaFuncAttributeMaxDynamicSharedMemorySize, GSMEM);
    }

    k_atom<<<(NN * 32 + 255) / 256, 256>>>(x, aemb, bemb);     // launch 0
    k_scatter<<<(EE + 255) / 256, 256>>>(src, dst, ea);        // launch 1
    k_clamp<<<(NN + 255) / 256, 256>>>();                      // launch 2

    int agg_blocks = sms * 5;
    for (int l = 0; l < 7; ++l) {
        const float* Wl  = W  + l * DD * DD;
        const float* bl  = b  + l * DD;
        const float* gl  = g  + l * DD;
        const float* btl = bt + l * DD;
        const float* hi = (l == 0) ? p_h : p_h2;
        k_agg<<<agg_blocks, 256>>>(hi);                        // launch 3 = agg0 (profiled)
        if (l == 0)
            k_gemm<false, false><<<sms, 512, GSMEM>>>(Wl, bl, gl, btl, out);
        else if (l < 6)
            k_gemm<true, false><<<sms, 512, GSMEM>>>(Wl, bl, gl, btl, out);
        else
            k_gemm<true, true><<<sms, 512, GSMEM>>>(Wl, bl, gl, btl, out);
    }
}

// round 9
// speedup vs baseline: 1.7261x; 1.4336x over previous
#include <cuda_runtime.h>
#include <cuda_bf16.h>
#include <cuda_pipeline_primitives.h>
#include <cstdint>
#include <math.h>

#define NN 50000
#define EE 625000
#define DD 128
#define MEPS 1e-7f
#define BSTRIDE 64
#define NTILES 391            // ceil(NN/128)

#define ATS   136             // bf16 elements per smem row (128 + 8 pad)
#define ATS_B 272             // row stride bytes
#define ATILE (128 * ATS_B)   // 34816 B per [128][136] bf16 tile

// ---- k_mma dynamic smem byte offsets ----------------------------------------
#define SM_BHI  0
#define SM_BLO  (SM_BHI + ATILE)             // 34816
#define SM_A    (SM_BLO + ATILE)             // 69632: buf0 hi, buf0 lo, buf1 hi, buf1 lo
#define SM_BIAS (SM_A + 4 * ATILE)           // 208896
#define SM_GAM  (SM_BIAS + 512)
#define SM_BET  (SM_GAM + 512)
#define SM_LNP  (SM_BET + 512)               // 128 rows x 4 warps x float2 = 4096
#define SM_TOTAL (SM_LNP + 4096)             // 214528 B (< 227 KB)

// ================= device scratch =============================================
__device__ __align__(16) float g_h [NN * DD];            // residual state / layer-0 input
__device__ __align__(16) float g_h2[NN * DD];            // relu(LN(h)) next conv input
__device__ __align__(16) __nv_bfloat16 g_Ahi[NN * DD];   // agg output hi (GEMM A)
__device__ __align__(16) __nv_bfloat16 g_Alo[NN * DD];   // agg output lo
__device__ __align__(16) float g_pair[64 * DD];          // (a0,a1) bond table
__device__ __align__(16) float g_b2  [8 * DD];           // bond feature-2 table
__device__ int g_cursor[NN];
__device__ int g_packed[NN * BSTRIDE];                   // src(16b)|a0<<16|a1<<19|a2<<22

// ================= helpers ====================================================
__device__ __forceinline__ uint32_t smem_to_u32(const void* smem_ptr) {
    uint32_t addr;
    asm("{ .reg .u64 tmp; cvta.to.shared.u64 tmp, %1; cvt.u32.u64 %0, tmp; }"
        : "=r"(addr) : "l"(smem_ptr));
    return addr;
}

__device__ __forceinline__ void ldsm4(uint32_t& r0, uint32_t& r1, uint32_t& r2,
                                      uint32_t& r3, uint32_t addr) {
    asm volatile("ldmatrix.sync.aligned.m8n8.x4.shared.b16 {%0,%1,%2,%3}, [%4];"
                 : "=r"(r0), "=r"(r1), "=r"(r2), "=r"(r3) : "r"(addr));
}

__device__ __forceinline__ void mma_bf16(float& d0, float& d1, float& d2, float& d3,
                                         uint32_t a0, uint32_t a1, uint32_t a2, uint32_t a3,
                                         uint32_t b0, uint32_t b1) {
    asm volatile("mma.sync.aligned.m16n8k16.row.col.f32.bf16.bf16.f32 "
                 "{%0,%1,%2,%3}, {%4,%5,%6,%7}, {%8,%9}, {%0,%1,%2,%3};"
                 : "+f"(d0), "+f"(d1), "+f"(d2), "+f"(d3)
                 : "r"(a0), "r"(a1), "r"(a2), "r"(a3), "r"(b0), "r"(b1));
}

__device__ __forceinline__ unsigned long long f2u(float2 v) {
    return *reinterpret_cast<unsigned long long*>(&v);
}
__device__ __forceinline__ float2 u2f2(unsigned long long v) {
    return *reinterpret_cast<float2*>(&v);
}
__device__ __forceinline__ float2 f2add(float2 a, float2 b) {
    unsigned long long d;
    asm("add.rn.f32x2 %0,%1,%2;" : "=l"(d) : "l"(f2u(a)), "l"(f2u(b)));
    return u2f2(d);
}
__device__ __forceinline__ float2 f2fma(float2 a, float2 b, float2 c) {
    unsigned long long d;
    asm("fma.rn.f32x2 %0,%1,%2,%3;" : "=l"(d) : "l"(f2u(a)), "l"(f2u(b)), "l"(f2u(c)));
    return u2f2(d);
}

__device__ __forceinline__ unsigned pack2(__nv_bfloat16 a, __nv_bfloat16 b) {
    __nv_bfloat162 t = __halves2bfloat162(a, b);
    return *reinterpret_cast<unsigned*>(&t);
}
__device__ __forceinline__ void bsplit(float v, __nv_bfloat16& hi, __nv_bfloat16& lo) {
    hi = __float2bfloat16(v);
    lo = __float2bfloat16(v - __bfloat162float(hi));
}

// ================= prep =======================================================
__global__ void k_atom(const int* __restrict__ x, const float* __restrict__ aemb,
                       const float* __restrict__ bemb) {
    int i = blockIdx.x * blockDim.x + threadIdx.x;   // NN*32 float4 slots
    if (i >= NN * 32) return;
    int n = i >> 5, q = i & 31;
    if (q == 0) g_cursor[n] = 0;
    if (i < 64 * 32) {                               // pair table: c = a0 | a1<<3
        int c = i >> 5, qq = i & 31;
        float4 u = ((const float4*)(bemb + ((c & 7)     ) * DD))[qq];
        float4 v = ((const float4*)(bemb + (8 + (c >> 3)) * DD))[qq];
        ((float4*)(g_pair + c * DD))[qq] =
            make_float4(u.x + v.x, u.y + v.y, u.z + v.z, u.w + v.w);
    }
    if (i < 8 * 32)
        ((float4*)g_b2)[i] = ((const float4*)(bemb + 16 * DD))[i];
    float4 s = make_float4(0.f, 0.f, 0.f, 0.f);
#pragma unroll
    for (int f = 0; f < 9; ++f) {
        int v = x[n * 9 + f];
        float4 t = ((const float4*)(aemb + (f * 64 + v) * DD))[q];
        s.x += t.x; s.y += t.y; s.z += t.z; s.w += t.w;
    }
    ((float4*)(g_h + n * DD))[q] = s;
}

__global__ void k_scatter(const int* __restrict__ src, const int* __restrict__ dst,
                          const int* __restrict__ ea) {
    int e = blockIdx.x * blockDim.x + threadIdx.x;
    if (e >= EE) return;
    int d = dst[e];
    int pos = atomicAdd(&g_cursor[d], 1);
    if (pos < BSTRIDE) {
        int p = src[e] | (ea[e * 3] << 16) | (ea[e * 3 + 1] << 19) | (ea[e * 3 + 2] << 22);
        g_packed[d * BSTRIDE + pos] = p;
    }
}

// ================= aggregation (persistent, warp/node, exact eps-hoist) =======
__global__ void __launch_bounds__(256, 5) k_agg(const float* __restrict__ hin) {
    __shared__ float SP[64 * DD];
    __shared__ float S2[8 * DD];
    int tid = threadIdx.x;
    for (int i = tid; i < 64 * 32; i += 256) ((float4*)SP)[i] = ((const float4*)g_pair)[i];
    if (tid < 8 * 32) ((float4*)S2)[tid] = ((const float4*)g_b2)[tid];
    __syncthreads();

    int warp = tid >> 5, lane = tid & 31;
    const float4* SPl = (const float4*)SP + lane;
    const float4* S2l = (const float4*)S2 + lane;
    const float4* Hl  = (const float4*)hin + lane;

    for (int n = blockIdx.x * 8 + warp; n < NN; n += gridDim.x * 8) {
        int deg = g_cursor[n]; if (deg > BSTRIDE) deg = BSTRIDE;
        int base = n * BSTRIDE;
        int pk0 = g_packed[base + lane];
        int pk1 = g_packed[base + 32 + lane];

        float2 den01 = make_float2(0.f, 0.f), den23 = make_float2(0.f, 0.f);
        float2 num01 = make_float2(0.f, 0.f), num23 = make_float2(0.f, 0.f);

        // exp(m̂+eps) factors cancel in num/den; Σα(m̂+eps) = Σα m̂ + eps — exact.
        auto proc = [&](int p) {
            const float4 hv = __ldg(Hl + (p & 0xFFFF) * 32);
            const float4 c  = SPl[((p >> 16) & 63) * 32];
            const float4 d  = S2l[((p >> 22) & 7) * 32];
            float2 t01 = f2add(make_float2(hv.x, hv.y), make_float2(c.x, c.y));
            float2 t23 = f2add(make_float2(hv.z, hv.w), make_float2(c.z, c.w));
            t01 = f2add(t01, make_float2(d.x, d.y));
            t23 = f2add(t23, make_float2(d.z, d.w));
            float2 m01 = make_float2(fmaxf(t01.x, 0.f), fmaxf(t01.y, 0.f));
            float2 m23 = make_float2(fmaxf(t23.x, 0.f), fmaxf(t23.y, 0.f));
            float2 e01 = make_float2(__expf(m01.x), __expf(m01.y));
            float2 e23 = make_float2(__expf(m23.x), __expf(m23.y));
            den01 = f2add(den01, e01);  den23 = f2add(den23, e23);
            num01 = f2fma(e01, m01, num01);  num23 = f2fma(e23, m23, num23);
        };

        int pairs = deg & ~1;
        for (int i = 0; i < pairs; i += 2) {
            int p0 = __shfl_sync(0xffffffffu, (i < 32) ? pk0 : pk1, i & 31);
            int j = i + 1;
            int p1 = __shfl_sync(0xffffffffu, (j < 32) ? pk0 : pk1, j & 31);
            proc(p0);
            proc(p1);
        }
        if (deg & 1) {
            int p = __shfl_sync(0xffffffffu, (pairs < 32) ? pk0 : pk1, pairs & 31);
            proc(p);
        }

        float4 hn = __ldg(Hl + n * 32);
        float4 o;
        float ofs = (deg > 0) ? MEPS : MEPS;   // +eps restored once (exact hoist)
        o.x = hn.x + num01.x / (den01.x + 1e-16f) + ofs;
        o.y = hn.y + num01.y / (den01.y + 1e-16f) + ofs;
        o.z = hn.z + num23.x / (den23.x + 1e-16f) + ofs;
        o.w = hn.w + num23.y / (den23.y + 1e-16f) + ofs;

        __nv_bfloat16 h0, h1, h2, h3, l0, l1, l2, l3;
        bsplit(o.x, h0, l0); bsplit(o.y, h1, l1);
        bsplit(o.z, h2, l2); bsplit(o.w, h3, l3);
        uint2 uh, ul;
        uh.x = pack2(h0, h1); uh.y = pack2(h2, h3);
        ul.x = pack2(l0, l1); ul.y = pack2(l2, l3);
        ((uint2*)(g_Ahi + n * DD))[lane] = uh;
        ((uint2*)(g_Alo + n * DD))[lane] = ul;
    }
}

// ================= A-tile prefetch (cp.async, zfill OOB rows) =================
__device__ __forceinline__ void prefetch_A(char* smc, int buf, int row0, int tid) {
    char* dsth = smc + SM_A + buf * (2 * ATILE);
    char* dstl = dsth + ATILE;
    for (int i = tid; i < 128 * 16; i += 512) {
        int r = i >> 4, ch = (i & 15) * 16;
        int grow = row0 + r;
        int gz = (grow < NN) ? 0 : 16;
        int gr = (grow < NN) ? grow : 0;
        __pipeline_memcpy_async(dsth + r * ATS_B + ch, (const char*)(g_Ahi + gr * DD) + ch, 16, gz);
        __pipeline_memcpy_async(dstl + r * ATS_B + ch, (const char*)(g_Alo + gr * DD) + ch, 16, gz);
    }
}

// ================= HMMA GEMM layer: D = A@W (bf16 split) + bias/res/LN ========
template <bool RES, bool FINAL>
__global__ void __launch_bounds__(512, 1) k_mma(const float* __restrict__ Wl,
                                                const float* __restrict__ bl,
                                                const float* __restrict__ gl,
                                                const float* __restrict__ btl,
                                                float* __restrict__ dout) {
    extern __shared__ char smc[];
    uint32_t sb = smem_to_u32(smc);
    int tid = threadIdx.x;
    int warp = tid >> 5, lane = tid & 31;
    int wm = warp >> 2, wn = warp & 3;      // 4x4 warp grid: 32-row x 32-col warp tiles

    // ---- prologue: W transpose+split into B[n][k], bias/gamma/beta, first A --
    for (int i = tid; i < 128 * 32; i += 512) {
        int k = i >> 5, q = i & 31;
        float4 w = *(const float4*)&Wl[k * DD + q * 4];
#pragma unroll
        for (int e = 0; e < 4; ++e) {
            int n = q * 4 + e;
            float val = (e == 0) ? w.x : (e == 1) ? w.y : (e == 2) ? w.z : w.w;
            __nv_bfloat16 hi, lo;
            bsplit(val, hi, lo);
            ((__nv_bfloat16*)(smc + SM_BHI))[n * ATS + k] = hi;
            ((__nv_bfloat16*)(smc + SM_BLO))[n * ATS + k] = lo;
        }
    }
    for (int i = tid; i < 128; i += 512) {
        ((float*)(smc + SM_BIAS))[i] = bl[i];
        ((float*)(smc + SM_GAM))[i]  = gl[i];
        ((float*)(smc + SM_BET))[i]  = btl[i];
    }
    prefetch_A(smc, 0, blockIdx.x * 128, tid);
    __pipeline_commit();
    __syncthreads();

    // per-lane ldmatrix offsets (verified PTX ISA fragment mappings)
    uint32_t a_loff = (uint32_t)(((lane & 15) * ATS + (lane >> 4) * 8) * 2);
    uint32_t b_loff = (uint32_t)((((lane & 7) + ((lane >> 4) & 1) * 8) * ATS
                                  + ((lane >> 3) & 1) * 8) * 2);
    uint32_t bhi_base = sb + SM_BHI + (uint32_t)(wn * 32 * ATS_B) + b_loff;
    uint32_t blo_base = sb + SM_BLO + (uint32_t)(wn * 32 * ATS_B) + b_loff;

    const float* bias  = (const float*)(smc + SM_BIAS);
    const float* gam   = (const float*)(smc + SM_GAM);
    const float* bet   = (const float*)(smc + SM_BET);
    float2* lnp        = (float2*)(smc + SM_LNP);

    int buf = 0;
    for (int t = blockIdx.x; t < NTILES; t += gridDim.x) {
        int row0 = t * 128;
        __pipeline_wait_prior(0);
        __syncthreads();

        int tn = t + (int)gridDim.x;
        if (tn < NTILES) prefetch_A(smc, buf ^ 1, tn * 128, tid);
        __pipeline_commit();

        uint32_t abase_hi = sb + SM_A + (uint32_t)(buf * 2 * ATILE) + a_loff
                          + (uint32_t)(wm * 32 * ATS_B);
        uint32_t abase_lo = abase_hi + (uint32_t)ATILE;

        float acc[2][4][4];
#pragma unroll
        for (int mt = 0; mt < 2; ++mt)
#pragma unroll
            for (int nt = 0; nt < 4; ++nt)
#pragma unroll
                for (int e = 0; e < 4; ++e) acc[mt][nt][e] = 0.f;

#pragma unroll
        for (int ks = 0; ks < 8; ++ks) {
            uint32_t kofs = (uint32_t)(ks * 32);
            uint32_t bh00, bh01, bh02, bh03, bh10, bh11, bh12, bh13;
            uint32_t bl00, bl01, bl02, bl03, bl10, bl11, bl12, bl13;
            ldsm4(bh00, bh01, bh02, bh03, bhi_base + kofs);
            ldsm4(bh10, bh11, bh12, bh13, bhi_base + 16 * ATS_B + kofs);
            ldsm4(bl00, bl01, bl02, bl03, blo_base + kofs);
            ldsm4(bl10, bl11, bl12, bl13, blo_base + 16 * ATS_B + kofs);
#pragma unroll
            for (int mt = 0; mt < 2; ++mt) {
                uint32_t arow = (uint32_t)(mt * 16 * ATS_B) + kofs;
                uint32_t ah0, ah1, ah2, ah3, al0, al1, al2, al3;
                ldsm4(ah0, ah1, ah2, ah3, abase_hi + arow);
                ldsm4(al0, al1, al2, al3, abase_lo + arow);
                // nt0: (bh00,bh01) ; nt1: (bh02,bh03) ; nt2: (bh10,bh11) ; nt3: (bh12,bh13)
                mma_bf16(acc[mt][0][0], acc[mt][0][1], acc[mt][0][2], acc[mt][0][3],
                         ah0, ah1, ah2, ah3, bh00, bh01);
                mma_bf16(acc[mt][0][0], acc[mt][0][1], acc[mt][0][2], acc[mt][0][3],
                         ah0, ah1, ah2, ah3, bl00, bl01);
                mma_bf16(acc[mt][0][0], acc[mt][0][1], acc[mt][0][2], acc[mt][0][3],
                         al0, al1, al2, al3, bh00, bh01);
                mma_bf16(acc[mt][1][0], acc[mt][1][1], acc[mt][1][2], acc[mt][1][3],
                         ah0, ah1, ah2, ah3, bh02, bh03);
                mma_bf16(acc[mt][1][0], acc[mt][1][1], acc[mt][1][2], acc[mt][1][3],
                         ah0, ah1, ah2, ah3, bl02, bl03);
                mma_bf16(acc[mt][1][0], acc[mt][1][1], acc[mt][1][2], acc[mt][1][3],
                         al0, al1, al2, al3, bh02, bh03);
                mma_bf16(acc[mt][2][0], acc[mt][2][1], acc[mt][2][2], acc[mt][2][3],
                         ah0, ah1, ah2, ah3, bh10, bh11);
                mma_bf16(acc[mt][2][0], acc[mt][2][1], acc[mt][2][2], acc[mt][2][3],
                         ah0, ah1, ah2, ah3, bl10, bl11);
                mma_bf16(acc[mt][2][0], acc[mt][2][1], acc[mt][2][2], acc[mt][2][3],
                         al0, al1, al2, al3, bh10, bh11);
                mma_bf16(acc[mt][3][0], acc[mt][3][1], acc[mt][3][2], acc[mt][3][3],
                         ah0, ah1, ah2, ah3, bh12, bh13);
                mma_bf16(acc[mt][3][0], acc[mt][3][1], acc[mt][3][2], acc[mt][3][3],
                         ah0, ah1, ah2, ah3, bl12, bl13);
                mma_bf16(acc[mt][3][0], acc[mt][3][1], acc[mt][3][2], acc[mt][3][3],
                         al0, al1, al2, al3, bh12, bh13);
            }
        }

        // ---- epilogue: bias (+residual), LN partials, normalize, store ----
        int l23 = lane >> 2;            // 0-7
        int lc  = (lane & 3) * 2;
#pragma unroll
        for (int mt = 0; mt < 2; ++mt) {
            int rl0 = wm * 32 + mt * 16 + l23;
            int rl1 = rl0 + 8;
            int gr0 = row0 + rl0, gr1 = row0 + rl1;
            int gc0 = (gr0 < NN) ? gr0 : 0;
            int gc1 = (gr1 < NN) ? gr1 : 0;
            float s0 = 0.f, q0 = 0.f, s1 = 0.f, q1 = 0.f;
#pragma unroll
            for (int nt = 0; nt < 4; ++nt) {
                int c = wn * 32 + nt * 8 + lc;
                float2 bv = *(const float2*)(bias + c);
                float v0 = acc[mt][nt][0] + bv.x;
                float v1 = acc[mt][nt][1] + bv.y;
                float v2 = acc[mt][nt][2] + bv.x;
                float v3 = acc[mt][nt][3] + bv.y;
                if (RES) {
                    float2 r0 = *(const float2*)&g_h[gc0 * DD + c];
                    float2 r1 = *(const float2*)&g_h[gc1 * DD + c];
                    v0 += r0.x; v1 += r0.y; v2 += r1.x; v3 += r1.y;
                }
                acc[mt][nt][0] = v0; acc[mt][nt][1] = v1;
                acc[mt][nt][2] = v2; acc[mt][nt][3] = v3;
                s0 += v0 + v1; q0 += v0 * v0 + v1 * v1;
                s1 += v2 + v3; q1 += v2 * v2 + v3 * v3;
            }
            s0 += __shfl_xor_sync(0xffffffffu, s0, 1); s0 += __shfl_xor_sync(0xffffffffu, s0, 2);
            q0 += __shfl_xor_sync(0xffffffffu, q0, 1); q0 += __shfl_xor_sync(0xffffffffu, q0, 2);
            s1 += __shfl_xor_sync(0xffffffffu, s1, 1); s1 += __shfl_xor_sync(0xffffffffu, s1, 2);
            q1 += __shfl_xor_sync(0xffffffffu, q1, 1); q1 += __shfl_xor_sync(0xffffffffu, q1, 2);
            if ((lane & 3) == 0) {
                lnp[rl0 * 4 + wn] = make_float2(s0, q0);
                lnp[rl1 * 4 + wn] = make_float2(s1, q1);
            }
        }
        __syncthreads();

#pragma unroll
        for (int mt = 0; mt < 2; ++mt) {
            int rl0 = wm * 32 + mt * 16 + l23;
            int rl1 = rl0 + 8;
            int gr0 = row0 + rl0, gr1 = row0 + rl1;
            float S0 = 0.f, Q0 = 0.f, S1 = 0.f, Q1 = 0.f;
#pragma unroll
            for (int w = 0; w < 4; ++w) {
                float2 p0 = lnp[rl0 * 4 + w]; S0 += p0.x; Q0 += p0.y;
                float2 p1 = lnp[rl1 * 4 + w]; S1 += p1.x; Q1 += p1.y;
            }
            float mu0 = S0 * (1.f / 128.f), mu1 = S1 * (1.f / 128.f);
            float rs0 = rsqrtf(Q0 * (1.f / 128.f) - mu0 * mu0 + 1e-5f);
            float rs1 = rsqrtf(Q1 * (1.f / 128.f) - mu1 * mu1 + 1e-5f);
#pragma unroll
            for (int nt = 0; nt < 4; ++nt) {
                int c = wn * 32 + nt * 8 + lc;
                float2 gv = *(const float2*)(gam + c);
                float2 tv = *(const float2*)(bet + c);
                float v0 = acc[mt][nt][0], v1 = acc[mt][nt][1];
                float v2 = acc[mt][nt][2], v3 = acc[mt][nt][3];
                float y0 = (v0 - mu0) * rs0 * gv.x + tv.x;
                float y1 = (v1 - mu0) * rs0 * gv.y + tv.y;
                float y2 = (v2 - mu1) * rs1 * gv.x + tv.x;
                float y3 = (v3 - mu1) * rs1 * gv.y + tv.y;
                if (gr0 < NN) {
                    if (FINAL) {
                        *(float2*)&dout[gr0 * DD + c] = make_float2(y0, y1);
                    } else {
                        *(float2*)&g_h [gr0 * DD + c] = make_float2(v0, v1);
                        *(float2*)&g_h2[gr0 * DD + c] = make_float2(fmaxf(y0, 0.f), fmaxf(y1, 0.f));
                    }
                }
                if (gr1 < NN) {
                    if (FINAL) {
                        *(float2*)&dout[gr1 * DD + c] = make_float2(y2, y3);
                    } else {
                        *(float2*)&g_h [gr1 * DD + c] = make_float2(v2, v3);
                        *(float2*)&g_h2[gr1 * DD + c] = make_float2(fmaxf(y2, 0.f), fmaxf(y3, 0.f));
                    }
                }
            }
        }
        __syncthreads();
        buf ^= 1;
    }
}

// ================= launch =====================================================
extern "C" void kernel_launch(void* const* d_in, const int* in_sizes, int n_in,
                              void* d_out, int out_size) {
    const int*   x    = (const int*)  d_in[0];
    const int*   ei   = (const int*)  d_in[1];
    const int*   ea   = (const int*)  d_in[2];
    const float* aemb = (const float*)d_in[3];
    const float* bemb = (const float*)d_in[4];
    const float* W    = (const float*)d_in[5];
    const float* b    = (const float*)d_in[6];
    const float* g    = (const float*)d_in[7];
    const float* bt   = (const float*)d_in[8];
    float* out = (float*)d_out;
    const int* src = ei;
    const int* dst = ei + EE;

    static float *p_h = nullptr, *p_h2 = nullptr;
    static int sms = 148;
    if (!p_h) {
        cudaGetSymbolAddress((void**)&p_h,  g_h);
        cudaGetSymbolAddress((void**)&p_h2, g_h2);
        cudaDeviceGetAttribute(&sms, cudaDevAttrMultiProcessorCount, 0);
        cudaFuncSetAttribute((const void*)k_mma<false, false>, cudaFuncAttributeMaxDynamicSharedMemorySize, SM_TOTAL);
        cudaFuncSetAttribute((const void*)k_mma<true,  false>, cudaFuncAttributeMaxDynamicSharedMemorySize, SM_TOTAL);
        cudaFuncSetAttribute((const void*)k_mma<true,  true >, cudaFuncAttributeMaxDynamicSharedMemorySize, SM_TOTAL);
    }

    k_atom<<<(NN * 32 + 255) / 256, 256>>>(x, aemb, bemb);     // launch 0
    k_scatter<<<(EE + 255) / 256, 256>>>(src, dst, ea);        // launch 1

    int agg_blocks = sms * 5;
    for (int l = 0; l < 7; ++l) {
        const float* Wl  = W  + l * DD * DD;
        const float* bl  = b  + l * DD;
        const float* gl  = g  + l * DD;
        const float* btl = bt + l * DD;
        const float* hi = (l == 0) ? p_h : p_h2;
        k_agg<<<agg_blocks, 256>>>(hi);                        // launch 2 = agg0
        if (l == 0)
            k_mma<false, false><<<sms, 512, SM_TOTAL>>>(Wl, bl, gl, btl, out);  // launch 3 (profiled)
        else if (l < 6)
            k_mma<true, false><<<sms, 512, SM_TOTAL>>>(Wl, bl, gl, btl, out);
        else
            k_mma<true, true><<<sms, 512, SM_TOTAL>>>(Wl, bl, gl, btl, out);
    }
}